// round 8
// baseline (speedup 1.0000x reference)
#include <cuda_runtime.h>
#include <cuda_bf16.h>
#include <stdint.h>
#include <math.h>

#define BATCH   2
#define SEQ     2048
#define EMB     1024
#define NHEAD   16
#define HDIM    64
#define MROWS   (BATCH * SEQ)
#define K3      (3 * EMB)
#define QKV_ELEMS (BATCH * NHEAD * SEQ * HDIM)

// Scratch (__device__ globals)
__device__ __nv_bfloat16 g_Qhi[QKV_ELEMS];
__device__ __nv_bfloat16 g_Qlo[QKV_ELEMS];
__device__ __nv_bfloat16 g_Khi[QKV_ELEMS];
__device__ __nv_bfloat16 g_Klo[QKV_ELEMS];
__device__ __nv_bfloat16 g_Vhi[QKV_ELEMS];
__device__ __nv_bfloat16 g_Vlo[QKV_ELEMS];
__device__ __nv_bfloat16 g_VThi[QKV_ELEMS];   // [B,H,D,S]
__device__ __nv_bfloat16 g_VTlo[QKV_ELEMS];
__device__ __nv_bfloat16 g_Xs[(size_t)MROWS * K3];
__device__ __nv_bfloat16 g_Ws[4][(size_t)EMB * K3];
__device__ __nv_bfloat16 g_As[(size_t)MROWS * K3];

// ---------------------------------------------------------------------------
__device__ __forceinline__ uint32_t smem_u32(const void* p) {
    uint32_t a;
    asm("{ .reg .u64 t; cvta.to.shared.u64 t, %1; cvt.u32.u64 %0, t; }" : "=r"(a) : "l"(p));
    return a;
}
#define CP_ASYNC16(dst, src) asm volatile("cp.async.cg.shared.global [%0], [%1], 16;" :: "r"(dst), "l"(src))
#define CP_COMMIT()  asm volatile("cp.async.commit_group;" ::: "memory")
#define CP_WAIT2()   asm volatile("cp.async.wait_group 2;" ::: "memory")
#define CP_WAIT1()   asm volatile("cp.async.wait_group 1;" ::: "memory")
#define CP_WAIT0()   asm volatile("cp.async.wait_group 0;" ::: "memory")

__device__ __forceinline__ void ldsm_x4(uint32_t& r0, uint32_t& r1, uint32_t& r2, uint32_t& r3,
                                        uint32_t addr)
{
    asm volatile("ldmatrix.sync.aligned.m8n8.x4.shared.b16 {%0,%1,%2,%3}, [%4];"
        : "=r"(r0), "=r"(r1), "=r"(r2), "=r"(r3) : "r"(addr));
}

__device__ __forceinline__ void hilo2(float x, float y, uint32_t& hi, uint32_t& lo)
{
    __nv_bfloat16 hx = __float2bfloat16(x), hy = __float2bfloat16(y);
    __nv_bfloat16 lx = __float2bfloat16(x - __bfloat162float(hx));
    __nv_bfloat16 ly = __float2bfloat16(y - __bfloat162float(hy));
    __nv_bfloat162 h2; h2.x = hx; h2.y = hy;
    __nv_bfloat162 l2; l2.x = lx; l2.y = ly;
    hi = *(uint32_t*)&h2;
    lo = *(uint32_t*)&l2;
}

__device__ __forceinline__ void mma16816(float* c, const uint32_t* a, const uint32_t* b)
{
    asm volatile(
        "mma.sync.aligned.m16n8k16.row.col.f32.bf16.bf16.f32 "
        "{%0,%1,%2,%3}, {%4,%5,%6,%7}, {%8,%9}, {%0,%1,%2,%3};"
        : "+f"(c[0]), "+f"(c[1]), "+f"(c[2]), "+f"(c[3])
        : "r"(a[0]), "r"(a[1]), "r"(a[2]), "r"(a[3]), "r"(b[0]), "r"(b[1]));
}

// ---------------------------------------------------------------------------
// Split conversion kernels
// ---------------------------------------------------------------------------
__global__ void split_x_kernel(const float* __restrict__ in,
                               __nv_bfloat16* __restrict__ out)
{
    int idx = blockIdx.x * blockDim.x + threadIdx.x;
    int r = idx >> 10;
    int k = idx & 1023;
    float x = in[idx];
    __nv_bfloat16 hi = __float2bfloat16(x);
    __nv_bfloat16 lo = __float2bfloat16(x - __bfloat162float(hi));
    __nv_bfloat16* o = out + (size_t)r * K3 + k;
    o[0] = hi; o[1024] = hi; o[2048] = lo;
}

__global__ void split_w_kernel(const float* __restrict__ W0, const float* __restrict__ W1,
                               const float* __restrict__ W2, const float* __restrict__ W3,
                               __nv_bfloat16* __restrict__ out)
{
    int w = blockIdx.y;
    const float* in = (w == 0) ? W0 : (w == 1) ? W1 : (w == 2) ? W2 : W3;
    int idx = blockIdx.x * blockDim.x + threadIdx.x;
    int r = idx >> 10;
    int k = idx & 1023;
    float x = in[idx];
    __nv_bfloat16 hi = __float2bfloat16(x);
    __nv_bfloat16 lo = __float2bfloat16(x - __bfloat162float(hi));
    __nv_bfloat16* o = out + (size_t)w * EMB * K3 + (size_t)r * K3 + k;
    o[0] = hi; o[1024] = lo; o[2048] = hi;
}

// ---------------------------------------------------------------------------
// V transpose: [B,H,S,D] -> [B,H,D,S]
// ---------------------------------------------------------------------------
__global__ void __launch_bounds__(256)
transpose_v_kernel(const __nv_bfloat16* __restrict__ Vhi, const __nv_bfloat16* __restrict__ Vlo,
                   __nv_bfloat16* __restrict__ VThi, __nv_bfloat16* __restrict__ VTlo)
{
    __shared__ __nv_bfloat16 t0[64][72];
    __shared__ __nv_bfloat16 t1[64][72];
    const int tid = threadIdx.x;
    const int st  = blockIdx.x * 64;
    const int bh  = blockIdx.y;
    const size_t bi = (size_t)bh * SEQ * HDIM;
    const size_t bo = (size_t)bh * HDIM * SEQ;

#pragma unroll
    for (int j = 0; j < 2; j++) {
        int id  = tid + j * 256;
        int row = id >> 3;
        int co  = (id & 7) * 8;
        *(uint4*)&t0[row][co] = *(const uint4*)&Vhi[bi + (size_t)(st + row) * HDIM + co];
        *(uint4*)&t1[row][co] = *(const uint4*)&Vlo[bi + (size_t)(st + row) * HDIM + co];
    }
    __syncthreads();

#pragma unroll
    for (int j = 0; j < 2; j++) {
        int id  = tid + j * 256;
        int d   = id >> 3;
        int co  = (id & 7) * 8;
        __nv_bfloat16 h[8], l[8];
#pragma unroll
        for (int e = 0; e < 8; e++) { h[e] = t0[co + e][d]; l[e] = t1[co + e][d]; }
        *(uint4*)&VThi[bo + (size_t)d * SEQ + st + co] = *(uint4*)h;
        *(uint4*)&VTlo[bo + (size_t)d * SEQ + st + co] = *(uint4*)l;
    }
}

// ---------------------------------------------------------------------------
// bf16 HMMA GEMM, K=3072, 128x128 tile, 8 warps, 3-stage cp.async, ldmatrix.
// ---------------------------------------------------------------------------
#define GPAD   40
#define KCH    32
#define NCHUNK (K3 / KCH)
#define G_SMEM (2 * 3 * 128 * GPAD * 2)

__global__ void __launch_bounds__(256, 2)
gemm_mma_kernel(const __nv_bfloat16* __restrict__ A,
                const __nv_bfloat16* __restrict__ B,
                const float* __restrict__ bias0, const float* __restrict__ bias1,
                const float* __restrict__ bias2,
                __nv_bfloat16* __restrict__ Qhi, __nv_bfloat16* __restrict__ Qlo,
                __nv_bfloat16* __restrict__ Khi, __nv_bfloat16* __restrict__ Klo,
                __nv_bfloat16* __restrict__ Vhi, __nv_bfloat16* __restrict__ Vlo,
                float* __restrict__ Cf, int mode)
{
    extern __shared__ __nv_bfloat16 smraw[];
    __nv_bfloat16 (*As)[128][GPAD] = reinterpret_cast<__nv_bfloat16(*)[128][GPAD]>(smraw);
    __nv_bfloat16 (*Bs)[128][GPAD] = reinterpret_cast<__nv_bfloat16(*)[128][GPAD]>(smraw + 3 * 128 * GPAD);

    const int tid  = threadIdx.x;
    const int wid  = tid >> 5;
    const int lane = tid & 31;
    const int g    = lane >> 2;
    const int t    = lane & 3;
    const int bm   = blockIdx.y;
    const int bn   = blockIdx.x;
    const int wm   = (wid >> 2) * 64;
    const int wn   = (wid & 3) * 32;

    const int arow = (lane & 7) + ((lane >> 3) & 1) * 8;
    const int acol = (lane >> 4) * 8;
    const int brow = (lane & 7) + ((lane >> 4) & 1) * 8;
    const int bcol = ((lane >> 3) & 1) * 8;

    const int lrow = tid >> 1;
    const int lco  = (tid & 1) * 16;
    const __nv_bfloat16* Ag = A + (size_t)(bm * 128 + lrow) * K3 + lco;
    const __nv_bfloat16* Bg = B + (size_t)(bn * 128 + lrow) * K3 + lco;
    const uint32_t dA = smem_u32(&As[0][lrow][lco]);
    const uint32_t dB = smem_u32(&Bs[0][lrow][lco]);
    const uint32_t stg_bytes = 128 * GPAD * 2;

    const uint32_t aBase = smem_u32(&As[0][0][0]);
    const uint32_t bBase = smem_u32(&Bs[0][0][0]);

    auto load_st = [&](int st, int k0) {
        CP_ASYNC16(dA + st * stg_bytes,      Ag + k0);
        CP_ASYNC16(dA + st * stg_bytes + 16, Ag + k0 + 8);
        CP_ASYNC16(dB + st * stg_bytes,      Bg + k0);
        CP_ASYNC16(dB + st * stg_bytes + 16, Bg + k0 + 8);
        CP_COMMIT();
    };

    float acc[4][4][4];
#pragma unroll
    for (int i = 0; i < 4; i++)
#pragma unroll
        for (int j = 0; j < 4; j++)
#pragma unroll
            for (int q = 0; q < 4; q++) acc[i][j][q] = 0.f;

    load_st(0, 0);
    load_st(1, KCH);

    for (int c = 0; c < NCHUNK; c++) {
        const int st = c % 3;
        if (c + 2 < NCHUNK) { load_st((c + 2) % 3, (c + 2) * KCH); CP_WAIT2(); }
        else if (c + 1 < NCHUNK) { CP_WAIT1(); }
        else { CP_WAIT0(); }
        __syncthreads();

        const uint32_t aS = aBase + st * stg_bytes;
        const uint32_t bS = bBase + st * stg_bytes;

#pragma unroll
        for (int kk = 0; kk < KCH; kk += 16) {
            uint32_t af[4][4], bf[4][2];
#pragma unroll
            for (int mi = 0; mi < 4; mi++) {
                uint32_t addr = aS + (((uint32_t)(wm + mi * 16 + arow)) * GPAD + kk + acol) * 2;
                ldsm_x4(af[mi][0], af[mi][1], af[mi][2], af[mi][3], addr);
            }
#pragma unroll
            for (int np = 0; np < 2; np++) {
                uint32_t addr = bS + (((uint32_t)(wn + np * 16 + brow)) * GPAD + kk + bcol) * 2;
                ldsm_x4(bf[2 * np][0], bf[2 * np][1], bf[2 * np + 1][0], bf[2 * np + 1][1], addr);
            }
#pragma unroll
            for (int mi = 0; mi < 4; mi++)
#pragma unroll
                for (int ni = 0; ni < 4; ni++)
                    mma16816(acc[mi][ni], af[mi], bf[ni]);
        }
        __syncthreads();
    }

#pragma unroll
    for (int mi = 0; mi < 4; mi++) {
        const int r0 = bm * 128 + wm + mi * 16 + g;
#pragma unroll
        for (int ni = 0; ni < 4; ni++) {
            const int c = bn * 128 + wn + ni * 8 + 2 * t;
            if (mode == 0) {
                const int which = c >> 10;
                const int cc    = c & 1023;
                const float* bp = (which == 0) ? bias0 : (which == 1) ? bias1 : bias2;
                const float bv0 = bp[cc], bv1 = bp[cc + 1];
                float v00 = acc[mi][ni][0] + bv0, v01 = acc[mi][ni][1] + bv1;
                float v10 = acc[mi][ni][2] + bv0, v11 = acc[mi][ni][3] + bv1;
                const int b = r0 >> 11, sq = r0 & 2047;
                const int h = cc >> 6, d = cc & 63;
                size_t off0 = (((size_t)(b * NHEAD + h) * SEQ) + sq) * HDIM + d;
                size_t off1 = off0 + 8 * HDIM;
                __nv_bfloat16* Hh = (which == 0) ? Qhi : (which == 1) ? Khi : Vhi;
                __nv_bfloat16* Ll = (which == 0) ? Qlo : (which == 1) ? Klo : Vlo;
                uint32_t hi0, lo0, hi1, lo1;
                hilo2(v00, v01, hi0, lo0);
                hilo2(v10, v11, hi1, lo1);
                *(uint32_t*)(Hh + off0) = hi0;
                *(uint32_t*)(Ll + off0) = lo0;
                *(uint32_t*)(Hh + off1) = hi1;
                *(uint32_t*)(Ll + off1) = lo1;
            } else {
                const float bv0 = bias0[c], bv1 = bias0[c + 1];
                *(float2*)(Cf + (size_t)r0 * EMB + c) =
                    make_float2(acc[mi][ni][0] + bv0, acc[mi][ni][1] + bv1);
                *(float2*)(Cf + (size_t)(r0 + 8) * EMB + c) =
                    make_float2(acc[mi][ni][2] + bv0, acc[mi][ni][3] + bv1);
            }
        }
    }
}

// ---------------------------------------------------------------------------
// Tensor-core flash attention v3: Br=128 per CTA (2 row-blocks/warp),
// cp.async double-buffer, ldmatrix with K/V fragment reuse across row-blocks.
// grid (SEQ/128 = 16, B*H = 32), block 128.
// ---------------------------------------------------------------------------
#define ASTR 72
#define A_STG (64 * ASTR)
#define ATT_SMEM (8 * A_STG * 2)

__global__ void __launch_bounds__(128, 2)
attn_mma_kernel(const __nv_bfloat16* __restrict__ Qhi, const __nv_bfloat16* __restrict__ Qlo,
                const __nv_bfloat16* __restrict__ Khi, const __nv_bfloat16* __restrict__ Klo,
                const __nv_bfloat16* __restrict__ VThi, const __nv_bfloat16* __restrict__ VTlo,
                __nv_bfloat16* __restrict__ Out)
{
    extern __shared__ __nv_bfloat16 sm[];
    __nv_bfloat16* sK  = sm;
    __nv_bfloat16* sVT = sm + 4 * A_STG;

    const int tid  = threadIdx.x;
    const int wid  = tid >> 5;
    const int lane = tid & 31;
    const int g    = lane >> 2;
    const int t    = lane & 3;
    const int qt   = blockIdx.x;
    const int bh   = blockIdx.y;
    const size_t base  = (size_t)bh * SEQ * HDIM;
    const size_t baseT = (size_t)bh * HDIM * SEQ;

    const int brow = (lane & 7) + ((lane >> 4) & 1) * 8;
    const int bcol = ((lane >> 3) & 1) * 8;

    // --- Stage Q (128 rows, hi then lo) into sK region, extract frags ---
    // layout: Qhi rows 0..127 at sm[0..2*A_STG), Qlo at sm[2*A_STG..4*A_STG)
#pragma unroll
    for (int i = 0; i < 8; i++) {
        int idx = tid + 128 * i;
        int row = idx >> 3;            // 0..127
        int co  = (idx & 7) * 8;
        *(uint4*)&sK[row * ASTR + co]             = *(const uint4*)&Qhi[base + (size_t)(qt * 128 + row) * HDIM + co];
        *(uint4*)&sK[2 * A_STG + row * ASTR + co] = *(const uint4*)&Qlo[base + (size_t)(qt * 128 + row) * HDIM + co];
    }
    __syncthreads();

    uint32_t qh[2][4][4], ql[2][4][4];
    {
        const int arow = (lane & 7) + ((lane >> 3) & 1) * 8;
        const int acol = (lane >> 4) * 8;
        const uint32_t qBase = smem_u32(sK);
#pragma unroll
        for (int rb = 0; rb < 2; rb++) {
#pragma unroll
            for (int kj = 0; kj < 4; kj++) {
                uint32_t ah = qBase + (((uint32_t)(wid * 32 + rb * 16 + arow)) * ASTR + 16 * kj + acol) * 2;
                ldsm_x4(qh[rb][kj][0], qh[rb][kj][1], qh[rb][kj][2], qh[rb][kj][3], ah);
                ldsm_x4(ql[rb][kj][0], ql[rb][kj][1], ql[rb][kj][2], ql[rb][kj][3], ah + 2 * A_STG * 2);
            }
        }
    }
    __syncthreads();

    const uint32_t sKa  = smem_u32(sK);
    const uint32_t sVTa = smem_u32(sVT);
    auto stage = [&](int st, int kt) {
#pragma unroll
        for (int j = 0; j < 4; j++) {
            int id  = tid + 128 * j;
            int row = id >> 3;
            int co  = (id & 7) * 8;
            uint32_t so = ((uint32_t)row * ASTR + co) * 2;
            CP_ASYNC16(sKa  + (st * 2 + 0) * A_STG * 2 + so, Khi  + base  + (size_t)(kt + row) * HDIM + co);
            CP_ASYNC16(sKa  + (st * 2 + 1) * A_STG * 2 + so, Klo  + base  + (size_t)(kt + row) * HDIM + co);
            CP_ASYNC16(sVTa + (st * 2 + 0) * A_STG * 2 + so, VThi + baseT + (size_t)row * SEQ + kt + co);
            CP_ASYNC16(sVTa + (st * 2 + 1) * A_STG * 2 + so, VTlo + baseT + (size_t)row * SEQ + kt + co);
        }
        CP_COMMIT();
    };

    float o[2][8][4];
#pragma unroll
    for (int rb = 0; rb < 2; rb++)
#pragma unroll
        for (int ni = 0; ni < 8; ni++)
#pragma unroll
            for (int j = 0; j < 4; j++) o[rb][ni][j] = 0.f;
    float m0[2] = {-1e30f, -1e30f}, m1[2] = {-1e30f, -1e30f};
    float l0[2] = {0.f, 0.f}, l1[2] = {0.f, 0.f};

    stage(0, 0);
    stage(1, 64);

    const int NT = SEQ / 64;
    for (int it = 0; it < NT; it++) {
        const int s = it & 1;
        if (it + 1 < NT) { CP_WAIT1(); } else { CP_WAIT0(); }
        __syncthreads();

        const uint32_t cKhiA = sKa  + (s * 2 + 0) * A_STG * 2;
        const uint32_t cKloA = sKa  + (s * 2 + 1) * A_STG * 2;
        const uint32_t cVhiA = sVTa + (s * 2 + 0) * A_STG * 2;
        const uint32_t cVloA = sVTa + (s * 2 + 1) * A_STG * 2;
        const uint32_t bOff  = ((uint32_t)brow * ASTR + bcol) * 2;

        // --- S = Q K^T (3 split terms), K frags shared across row-blocks ---
        float sc[2][8][4];
#pragma unroll
        for (int rb = 0; rb < 2; rb++)
#pragma unroll
            for (int ni = 0; ni < 8; ni++)
#pragma unroll
                for (int j = 0; j < 4; j++) sc[rb][ni][j] = 0.f;

#pragma unroll
        for (int kj = 0; kj < 4; kj++) {
#pragma unroll
            for (int np = 0; np < 4; np++) {
                uint32_t off = bOff + ((uint32_t)np * 16 * ASTR + 16 * kj) * 2;
                uint32_t h0[2], h1[2], w0[2], w1[2];
                ldsm_x4(h0[0], h0[1], h1[0], h1[1], cKhiA + off);
                ldsm_x4(w0[0], w0[1], w1[0], w1[1], cKloA + off);
#pragma unroll
                for (int rb = 0; rb < 2; rb++) {
                    mma16816(sc[rb][2 * np],     qh[rb][kj], h0);
                    mma16816(sc[rb][2 * np],     qh[rb][kj], w0);
                    mma16816(sc[rb][2 * np],     ql[rb][kj], h0);
                    mma16816(sc[rb][2 * np + 1], qh[rb][kj], h1);
                    mma16816(sc[rb][2 * np + 1], qh[rb][kj], w1);
                    mma16816(sc[rb][2 * np + 1], ql[rb][kj], h1);
                }
            }
        }

        // --- online softmax per row-block ---
#pragma unroll
        for (int rb = 0; rb < 2; rb++) {
            float mx0 = -1e30f, mx1 = -1e30f;
#pragma unroll
            for (int ni = 0; ni < 8; ni++) {
                sc[rb][ni][0] *= 0.125f; sc[rb][ni][1] *= 0.125f;
                sc[rb][ni][2] *= 0.125f; sc[rb][ni][3] *= 0.125f;
                mx0 = fmaxf(mx0, fmaxf(sc[rb][ni][0], sc[rb][ni][1]));
                mx1 = fmaxf(mx1, fmaxf(sc[rb][ni][2], sc[rb][ni][3]));
            }
            mx0 = fmaxf(mx0, __shfl_xor_sync(0xffffffff, mx0, 1));
            mx0 = fmaxf(mx0, __shfl_xor_sync(0xffffffff, mx0, 2));
            mx1 = fmaxf(mx1, __shfl_xor_sync(0xffffffff, mx1, 1));
            mx1 = fmaxf(mx1, __shfl_xor_sync(0xffffffff, mx1, 2));

            const float nm0 = fmaxf(m0[rb], mx0);
            const float nm1 = fmaxf(m1[rb], mx1);
            const float rs0 = __expf(m0[rb] - nm0);
            const float rs1 = __expf(m1[rb] - nm1);
            m0[rb] = nm0; m1[rb] = nm1;
            l0[rb] *= rs0; l1[rb] *= rs1;
#pragma unroll
            for (int ni = 0; ni < 8; ni++) {
                o[rb][ni][0] *= rs0; o[rb][ni][1] *= rs0;
                o[rb][ni][2] *= rs1; o[rb][ni][3] *= rs1;
                sc[rb][ni][0] = __expf(sc[rb][ni][0] - nm0);
                sc[rb][ni][1] = __expf(sc[rb][ni][1] - nm0);
                sc[rb][ni][2] = __expf(sc[rb][ni][2] - nm1);
                sc[rb][ni][3] = __expf(sc[rb][ni][3] - nm1);
                l0[rb] += sc[rb][ni][0] + sc[rb][ni][1];
                l1[rb] += sc[rb][ni][2] + sc[rb][ni][3];
            }
        }

        // --- O += P V (3 split terms), V frags shared across row-blocks ---
#pragma unroll
        for (int kj = 0; kj < 4; kj++) {
            uint32_t ah[2][4], al[2][4];
#pragma unroll
            for (int rb = 0; rb < 2; rb++) {
                hilo2(sc[rb][2 * kj][0],     sc[rb][2 * kj][1],     ah[rb][0], al[rb][0]);
                hilo2(sc[rb][2 * kj][2],     sc[rb][2 * kj][3],     ah[rb][1], al[rb][1]);
                hilo2(sc[rb][2 * kj + 1][0], sc[rb][2 * kj + 1][1], ah[rb][2], al[rb][2]);
                hilo2(sc[rb][2 * kj + 1][2], sc[rb][2 * kj + 1][3], ah[rb][3], al[rb][3]);
            }
#pragma unroll
            for (int np = 0; np < 4; np++) {
                uint32_t off = bOff + ((uint32_t)np * 16 * ASTR + 16 * kj) * 2;
                uint32_t h0[2], h1[2], w0[2], w1[2];
                ldsm_x4(h0[0], h0[1], h1[0], h1[1], cVhiA + off);
                ldsm_x4(w0[0], w0[1], w1[0], w1[1], cVloA + off);
#pragma unroll
                for (int rb = 0; rb < 2; rb++) {
                    mma16816(o[rb][2 * np],     ah[rb], h0);
                    mma16816(o[rb][2 * np],     ah[rb], w0);
                    mma16816(o[rb][2 * np],     al[rb], h0);
                    mma16816(o[rb][2 * np + 1], ah[rb], h1);
                    mma16816(o[rb][2 * np + 1], ah[rb], w1);
                    mma16816(o[rb][2 * np + 1], al[rb], h1);
                }
            }
        }

        __syncthreads();
        if (it + 2 < NT) stage(s, (it + 2) * 64);
    }

    // --- finalize ---
    const int b = bh >> 4;
    const int h = bh & 15;
#pragma unroll
    for (int rb = 0; rb < 2; rb++) {
        float a0 = l0[rb], a1 = l1[rb];
        a0 += __shfl_xor_sync(0xffffffff, a0, 1);
        a0 += __shfl_xor_sync(0xffffffff, a0, 2);
        a1 += __shfl_xor_sync(0xffffffff, a1, 1);
        a1 += __shfl_xor_sync(0xffffffff, a1, 2);
        const float inv0 = 1.f / a0;
        const float inv1 = 1.f / a1;

        const int s0 = qt * 128 + wid * 32 + rb * 16 + g;
        const size_t row0 = (size_t)(b * SEQ + s0) * K3;
        const size_t row1 = row0 + (size_t)8 * K3;

#pragma unroll
        for (int ni = 0; ni < 8; ni++) {
            const int col = h * 64 + 8 * ni + 2 * t;
            uint32_t hi0, lo0, hi1, lo1;
            hilo2(o[rb][ni][0] * inv0, o[rb][ni][1] * inv0, hi0, lo0);
            hilo2(o[rb][ni][2] * inv1, o[rb][ni][3] * inv1, hi1, lo1);
            *(uint32_t*)&Out[row0 + col]        = hi0;
            *(uint32_t*)&Out[row0 + col + 1024] = hi0;
            *(uint32_t*)&Out[row0 + col + 2048] = lo0;
            *(uint32_t*)&Out[row1 + col]        = hi1;
            *(uint32_t*)&Out[row1 + col + 1024] = hi1;
            *(uint32_t*)&Out[row1 + col + 2048] = lo1;
        }
    }
}

// ---------------------------------------------------------------------------
extern "C" void kernel_launch(void* const* d_in, const int* in_sizes, int n_in,
                              void* d_out, int out_size)
{
    const float* X   = (const float*)d_in[0];
    const float* W_q = (const float*)d_in[1];
    const float* b_q = (const float*)d_in[2];
    const float* W_k = (const float*)d_in[3];
    const float* b_k = (const float*)d_in[4];
    const float* W_v = (const float*)d_in[5];
    const float* b_v = (const float*)d_in[6];
    const float* W_o = (const float*)d_in[7];
    const float* b_o = (const float*)d_in[8];
    float* out = (float*)d_out;

    __nv_bfloat16 *Qhi, *Qlo, *Khi, *Klo, *Vhi, *Vlo, *VThi, *VTlo, *Xs, *Ws, *As;
    cudaGetSymbolAddress((void**)&Qhi, g_Qhi);
    cudaGetSymbolAddress((void**)&Qlo, g_Qlo);
    cudaGetSymbolAddress((void**)&Khi, g_Khi);
    cudaGetSymbolAddress((void**)&Klo, g_Klo);
    cudaGetSymbolAddress((void**)&Vhi, g_Vhi);
    cudaGetSymbolAddress((void**)&Vlo, g_Vlo);
    cudaGetSymbolAddress((void**)&VThi, g_VThi);
    cudaGetSymbolAddress((void**)&VTlo, g_VTlo);
    cudaGetSymbolAddress((void**)&Xs, g_Xs);
    cudaGetSymbolAddress((void**)&Ws, g_Ws);
    cudaGetSymbolAddress((void**)&As, g_As);

    cudaFuncSetAttribute(gemm_mma_kernel, cudaFuncAttributeMaxDynamicSharedMemorySize, G_SMEM);
    cudaFuncSetAttribute(attn_mma_kernel, cudaFuncAttributeMaxDynamicSharedMemorySize, ATT_SMEM);

    const int cthr = 256;
    split_x_kernel<<<MROWS * EMB / cthr, cthr>>>(X, Xs);
    dim3 wgrid(EMB * EMB / cthr, 4);
    split_w_kernel<<<wgrid, cthr>>>(W_q, W_k, W_v, W_o, Ws);

    dim3 qkvgrid(K3 / 128, MROWS / 128);
    gemm_mma_kernel<<<qkvgrid, 256, G_SMEM>>>(Xs, Ws, b_q, b_k, b_v,
                                              Qhi, Qlo, Khi, Klo, Vhi, Vlo, nullptr, 0);

    dim3 tgrid(SEQ / 64, BATCH * NHEAD);
    transpose_v_kernel<<<tgrid, 256>>>(Vhi, Vlo, VThi, VTlo);

    dim3 agrid(SEQ / 128, BATCH * NHEAD);
    attn_mma_kernel<<<agrid, 128, ATT_SMEM>>>(Qhi, Qlo, Khi, Klo, VThi, VTlo, As);

    dim3 ogrid(EMB / 128, MROWS / 128);
    gemm_mma_kernel<<<ogrid, 256, G_SMEM>>>(As, Ws + 3 * (size_t)EMB * K3, b_o, nullptr, nullptr,
                                            nullptr, nullptr, nullptr, nullptr, nullptr, nullptr,
                                            out, 1);
}

// round 9
// speedup vs baseline: 1.0427x; 1.0427x over previous
#include <cuda_runtime.h>
#include <cuda_bf16.h>
#include <stdint.h>
#include <math.h>

#define BATCH   2
#define SEQ     2048
#define EMB     1024
#define NHEAD   16
#define HDIM    64
#define MROWS   (BATCH * SEQ)
#define K3      (3 * EMB)
#define QKV_ELEMS (BATCH * NHEAD * SEQ * HDIM)

// Scratch (__device__ globals)
__device__ __nv_bfloat16 g_Qhi[QKV_ELEMS];
__device__ __nv_bfloat16 g_Qlo[QKV_ELEMS];
__device__ __nv_bfloat16 g_Khi[QKV_ELEMS];
__device__ __nv_bfloat16 g_Klo[QKV_ELEMS];
__device__ __nv_bfloat16 g_VThi[QKV_ELEMS];   // [B,H,D,S]
__device__ __nv_bfloat16 g_VTlo[QKV_ELEMS];
__device__ __nv_bfloat16 g_Xs[(size_t)MROWS * K3];
__device__ __nv_bfloat16 g_Ws[4][(size_t)EMB * K3];
__device__ __nv_bfloat16 g_As[(size_t)MROWS * K3];

// ---------------------------------------------------------------------------
__device__ __forceinline__ uint32_t smem_u32(const void* p) {
    uint32_t a;
    asm("{ .reg .u64 t; cvta.to.shared.u64 t, %1; cvt.u32.u64 %0, t; }" : "=r"(a) : "l"(p));
    return a;
}
#define CP_ASYNC16(dst, src) asm volatile("cp.async.cg.shared.global [%0], [%1], 16;" :: "r"(dst), "l"(src))
#define CP_COMMIT()  asm volatile("cp.async.commit_group;" ::: "memory")
#define CP_WAIT2()   asm volatile("cp.async.wait_group 2;" ::: "memory")
#define CP_WAIT1()   asm volatile("cp.async.wait_group 1;" ::: "memory")
#define CP_WAIT0()   asm volatile("cp.async.wait_group 0;" ::: "memory")

__device__ __forceinline__ void ldsm_x4(uint32_t& r0, uint32_t& r1, uint32_t& r2, uint32_t& r3,
                                        uint32_t addr)
{
    asm volatile("ldmatrix.sync.aligned.m8n8.x4.shared.b16 {%0,%1,%2,%3}, [%4];"
        : "=r"(r0), "=r"(r1), "=r"(r2), "=r"(r3) : "r"(addr));
}

__device__ __forceinline__ void hilo2(float x, float y, uint32_t& hi, uint32_t& lo)
{
    __nv_bfloat16 hx = __float2bfloat16(x), hy = __float2bfloat16(y);
    __nv_bfloat16 lx = __float2bfloat16(x - __bfloat162float(hx));
    __nv_bfloat16 ly = __float2bfloat16(y - __bfloat162float(hy));
    __nv_bfloat162 h2; h2.x = hx; h2.y = hy;
    __nv_bfloat162 l2; l2.x = lx; l2.y = ly;
    hi = *(uint32_t*)&h2;
    lo = *(uint32_t*)&l2;
}

__device__ __forceinline__ void hilo1(float x, __nv_bfloat16& h, __nv_bfloat16& l)
{
    h = __float2bfloat16(x);
    l = __float2bfloat16(x - __bfloat162float(h));
}

__device__ __forceinline__ void mma16816(float* c, const uint32_t* a, const uint32_t* b)
{
    asm volatile(
        "mma.sync.aligned.m16n8k16.row.col.f32.bf16.bf16.f32 "
        "{%0,%1,%2,%3}, {%4,%5,%6,%7}, {%8,%9}, {%0,%1,%2,%3};"
        : "+f"(c[0]), "+f"(c[1]), "+f"(c[2]), "+f"(c[3])
        : "r"(a[0]), "r"(a[1]), "r"(a[2]), "r"(a[3]), "r"(b[0]), "r"(b[1]));
}

// ---------------------------------------------------------------------------
// Split conversion kernels
// ---------------------------------------------------------------------------
__global__ void split_x_kernel(const float* __restrict__ in,
                               __nv_bfloat16* __restrict__ out)
{
    int idx = blockIdx.x * blockDim.x + threadIdx.x;
    int r = idx >> 10;
    int k = idx & 1023;
    float x = in[idx];
    __nv_bfloat16 hi = __float2bfloat16(x);
    __nv_bfloat16 lo = __float2bfloat16(x - __bfloat162float(hi));
    __nv_bfloat16* o = out + (size_t)r * K3 + k;
    o[0] = hi; o[1024] = hi; o[2048] = lo;
}

__global__ void split_w_kernel(const float* __restrict__ W0, const float* __restrict__ W1,
                               const float* __restrict__ W2, const float* __restrict__ W3,
                               __nv_bfloat16* __restrict__ out)
{
    int w = blockIdx.y;
    const float* in = (w == 0) ? W0 : (w == 1) ? W1 : (w == 2) ? W2 : W3;
    int idx = blockIdx.x * blockDim.x + threadIdx.x;
    int r = idx >> 10;
    int k = idx & 1023;
    float x = in[idx];
    __nv_bfloat16 hi = __float2bfloat16(x);
    __nv_bfloat16 lo = __float2bfloat16(x - __bfloat162float(hi));
    __nv_bfloat16* o = out + (size_t)w * EMB * K3 + (size_t)r * K3 + k;
    o[0] = hi; o[1024] = lo; o[2048] = hi;
}

// ---------------------------------------------------------------------------
// bf16 HMMA GEMM, K=3072, 128x128 tile, 8 warps, 3-stage cp.async, ldmatrix.
// mode 0: fused QKV; Q/K written split [B,H,S,D], V written split TRANSPOSED
//         [B,H,D,S] (fuses the V transpose into the epilogue).
// mode 1: O-projection, fp32 row-major.
// ---------------------------------------------------------------------------
#define GPAD   40
#define KCH    32
#define NCHUNK (K3 / KCH)
#define G_SMEM (2 * 3 * 128 * GPAD * 2)

__global__ void __launch_bounds__(256, 2)
gemm_mma_kernel(const __nv_bfloat16* __restrict__ A,
                const __nv_bfloat16* __restrict__ B,
                const float* __restrict__ bias0, const float* __restrict__ bias1,
                const float* __restrict__ bias2,
                __nv_bfloat16* __restrict__ Qhi, __nv_bfloat16* __restrict__ Qlo,
                __nv_bfloat16* __restrict__ Khi, __nv_bfloat16* __restrict__ Klo,
                __nv_bfloat16* __restrict__ VThi, __nv_bfloat16* __restrict__ VTlo,
                float* __restrict__ Cf, int mode)
{
    extern __shared__ __nv_bfloat16 smraw[];
    __nv_bfloat16 (*As)[128][GPAD] = reinterpret_cast<__nv_bfloat16(*)[128][GPAD]>(smraw);
    __nv_bfloat16 (*Bs)[128][GPAD] = reinterpret_cast<__nv_bfloat16(*)[128][GPAD]>(smraw + 3 * 128 * GPAD);

    const int tid  = threadIdx.x;
    const int wid  = tid >> 5;
    const int lane = tid & 31;
    const int g    = lane >> 2;
    const int t    = lane & 3;
    const int bm   = blockIdx.y;
    const int bn   = blockIdx.x;
    const int wm   = (wid >> 2) * 64;
    const int wn   = (wid & 3) * 32;

    const int arow = (lane & 7) + ((lane >> 3) & 1) * 8;
    const int acol = (lane >> 4) * 8;
    const int brow = (lane & 7) + ((lane >> 4) & 1) * 8;
    const int bcol = ((lane >> 3) & 1) * 8;

    const int lrow = tid >> 1;
    const int lco  = (tid & 1) * 16;
    const __nv_bfloat16* Ag = A + (size_t)(bm * 128 + lrow) * K3 + lco;
    const __nv_bfloat16* Bg = B + (size_t)(bn * 128 + lrow) * K3 + lco;
    const uint32_t dA = smem_u32(&As[0][lrow][lco]);
    const uint32_t dB = smem_u32(&Bs[0][lrow][lco]);
    const uint32_t stg_bytes = 128 * GPAD * 2;

    const uint32_t aBase = smem_u32(&As[0][0][0]);
    const uint32_t bBase = smem_u32(&Bs[0][0][0]);

    auto load_st = [&](int st, int k0) {
        CP_ASYNC16(dA + st * stg_bytes,      Ag + k0);
        CP_ASYNC16(dA + st * stg_bytes + 16, Ag + k0 + 8);
        CP_ASYNC16(dB + st * stg_bytes,      Bg + k0);
        CP_ASYNC16(dB + st * stg_bytes + 16, Bg + k0 + 8);
        CP_COMMIT();
    };

    float acc[4][4][4];
#pragma unroll
    for (int i = 0; i < 4; i++)
#pragma unroll
        for (int j = 0; j < 4; j++)
#pragma unroll
            for (int q = 0; q < 4; q++) acc[i][j][q] = 0.f;

    load_st(0, 0);
    load_st(1, KCH);

    for (int c = 0; c < NCHUNK; c++) {
        const int st = c % 3;
        if (c + 2 < NCHUNK) { load_st((c + 2) % 3, (c + 2) * KCH); CP_WAIT2(); }
        else if (c + 1 < NCHUNK) { CP_WAIT1(); }
        else { CP_WAIT0(); }
        __syncthreads();

        const uint32_t aS = aBase + st * stg_bytes;
        const uint32_t bS = bBase + st * stg_bytes;

#pragma unroll
        for (int kk = 0; kk < KCH; kk += 16) {
            uint32_t af[4][4], bf[4][2];
#pragma unroll
            for (int mi = 0; mi < 4; mi++) {
                uint32_t addr = aS + (((uint32_t)(wm + mi * 16 + arow)) * GPAD + kk + acol) * 2;
                ldsm_x4(af[mi][0], af[mi][1], af[mi][2], af[mi][3], addr);
            }
#pragma unroll
            for (int np = 0; np < 2; np++) {
                uint32_t addr = bS + (((uint32_t)(wn + np * 16 + brow)) * GPAD + kk + bcol) * 2;
                ldsm_x4(bf[2 * np][0], bf[2 * np][1], bf[2 * np + 1][0], bf[2 * np + 1][1], addr);
            }
#pragma unroll
            for (int mi = 0; mi < 4; mi++)
#pragma unroll
                for (int ni = 0; ni < 4; ni++)
                    mma16816(acc[mi][ni], af[mi], bf[ni]);
        }
        __syncthreads();
    }

#pragma unroll
    for (int mi = 0; mi < 4; mi++) {
        const int r0 = bm * 128 + wm + mi * 16 + g;
#pragma unroll
        for (int ni = 0; ni < 4; ni++) {
            const int c = bn * 128 + wn + ni * 8 + 2 * t;
            if (mode == 0) {
                const int which = c >> 10;
                const int cc    = c & 1023;
                const float* bp = (which == 0) ? bias0 : (which == 1) ? bias1 : bias2;
                const float bv0 = bp[cc], bv1 = bp[cc + 1];
                float v00 = acc[mi][ni][0] + bv0, v01 = acc[mi][ni][1] + bv1;
                float v10 = acc[mi][ni][2] + bv0, v11 = acc[mi][ni][3] + bv1;
                const int b = r0 >> 11, sq = r0 & 2047;
                const int h = cc >> 6, d = cc & 63;
                if (which < 2) {
                    // Q or K: [B,H,S,D] split layout
                    size_t off0 = (((size_t)(b * NHEAD + h) * SEQ) + sq) * HDIM + d;
                    size_t off1 = off0 + 8 * HDIM;
                    __nv_bfloat16* Hh = (which == 0) ? Qhi : Khi;
                    __nv_bfloat16* Ll = (which == 0) ? Qlo : Klo;
                    uint32_t hi0, lo0, hi1, lo1;
                    hilo2(v00, v01, hi0, lo0);
                    hilo2(v10, v11, hi1, lo1);
                    *(uint32_t*)(Hh + off0) = hi0;
                    *(uint32_t*)(Ll + off0) = lo0;
                    *(uint32_t*)(Hh + off1) = hi1;
                    *(uint32_t*)(Ll + off1) = lo1;
                } else {
                    // V: write TRANSPOSED [B,H,D,S] split layout
                    size_t offT = (((size_t)(b * NHEAD + h) * HDIM) + d) * SEQ + sq;
                    __nv_bfloat16 h00, l00, h01, l01, h10, l10, h11, l11;
                    hilo1(v00, h00, l00);   // (sq,   d)
                    hilo1(v01, h01, l01);   // (sq,   d+1)
                    hilo1(v10, h10, l10);   // (sq+8, d)
                    hilo1(v11, h11, l11);   // (sq+8, d+1)
                    VThi[offT]           = h00;
                    VThi[offT + 8]       = h10;
                    VThi[offT + SEQ]     = h01;
                    VThi[offT + SEQ + 8] = h11;
                    VTlo[offT]           = l00;
                    VTlo[offT + 8]       = l10;
                    VTlo[offT + SEQ]     = l01;
                    VTlo[offT + SEQ + 8] = l11;
                }
            } else {
                const float bv0 = bias0[c], bv1 = bias0[c + 1];
                *(float2*)(Cf + (size_t)r0 * EMB + c) =
                    make_float2(acc[mi][ni][0] + bv0, acc[mi][ni][1] + bv1);
                *(float2*)(Cf + (size_t)(r0 + 8) * EMB + c) =
                    make_float2(acc[mi][ni][2] + bv0, acc[mi][ni][3] + bv1);
            }
        }
    }
}

// ---------------------------------------------------------------------------
// Tensor-core flash attention (R7-exact): Br=64, cp.async double-buffer,
// ldmatrix frags, occ 3. grid (SEQ/64, B*H), block 128.
// ---------------------------------------------------------------------------
#define ASTR 72
#define A_STG (64 * ASTR)
#define ATT_SMEM (8 * A_STG * 2)

__global__ void __launch_bounds__(128, 3)
attn_mma_kernel(const __nv_bfloat16* __restrict__ Qhi, const __nv_bfloat16* __restrict__ Qlo,
                const __nv_bfloat16* __restrict__ Khi, const __nv_bfloat16* __restrict__ Klo,
                const __nv_bfloat16* __restrict__ VThi, const __nv_bfloat16* __restrict__ VTlo,
                __nv_bfloat16* __restrict__ Out)
{
    extern __shared__ __nv_bfloat16 sm[];
    __nv_bfloat16* sK  = sm;
    __nv_bfloat16* sVT = sm + 4 * A_STG;

    const int tid  = threadIdx.x;
    const int wid  = tid >> 5;
    const int lane = tid & 31;
    const int g    = lane >> 2;
    const int t    = lane & 3;
    const int qt   = blockIdx.x;
    const int bh   = blockIdx.y;
    const size_t base  = (size_t)bh * SEQ * HDIM;
    const size_t baseT = (size_t)bh * HDIM * SEQ;

    const int brow = (lane & 7) + ((lane >> 4) & 1) * 8;
    const int bcol = ((lane >> 3) & 1) * 8;

    // --- Stage Q tile into sK stage 0, extract frags ---
#pragma unroll
    for (int i = 0; i < 4; i++) {
        int idx = tid + 128 * i;
        int row = idx >> 3;
        int co  = (idx & 7) * 8;
        *(uint4*)&sK[row * ASTR + co]         = *(const uint4*)&Qhi[base + (size_t)(qt * 64 + row) * HDIM + co];
        *(uint4*)&sK[A_STG + row * ASTR + co] = *(const uint4*)&Qlo[base + (size_t)(qt * 64 + row) * HDIM + co];
    }
    __syncthreads();

    uint32_t qh[4][4], ql[4][4];
    {
        const int arow = (lane & 7) + ((lane >> 3) & 1) * 8;
        const int acol = (lane >> 4) * 8;
        const uint32_t qBase = smem_u32(sK);
#pragma unroll
        for (int kj = 0; kj < 4; kj++) {
            uint32_t ah = qBase + (((uint32_t)(wid * 16 + arow)) * ASTR + 16 * kj + acol) * 2;
            ldsm_x4(qh[kj][0], qh[kj][1], qh[kj][2], qh[kj][3], ah);
            ldsm_x4(ql[kj][0], ql[kj][1], ql[kj][2], ql[kj][3], ah + A_STG * 2);
        }
    }
    __syncthreads();

    const uint32_t sKa  = smem_u32(sK);
    const uint32_t sVTa = smem_u32(sVT);
    auto stage = [&](int st, int kt) {
#pragma unroll
        for (int j = 0; j < 4; j++) {
            int id  = tid + 128 * j;
            int row = id >> 3;
            int co  = (id & 7) * 8;
            uint32_t so = ((uint32_t)row * ASTR + co) * 2;
            CP_ASYNC16(sKa  + (st * 2 + 0) * A_STG * 2 + so, Khi  + base  + (size_t)(kt + row) * HDIM + co);
            CP_ASYNC16(sKa  + (st * 2 + 1) * A_STG * 2 + so, Klo  + base  + (size_t)(kt + row) * HDIM + co);
            CP_ASYNC16(sVTa + (st * 2 + 0) * A_STG * 2 + so, VThi + baseT + (size_t)row * SEQ + kt + co);
            CP_ASYNC16(sVTa + (st * 2 + 1) * A_STG * 2 + so, VTlo + baseT + (size_t)row * SEQ + kt + co);
        }
        CP_COMMIT();
    };

    float o[8][4];
#pragma unroll
    for (int ni = 0; ni < 8; ni++)
#pragma unroll
        for (int j = 0; j < 4; j++) o[ni][j] = 0.f;
    float m0 = -1e30f, m1 = -1e30f, l0 = 0.f, l1 = 0.f;

    stage(0, 0);
    stage(1, 64);

    const int NT = SEQ / 64;
    for (int it = 0; it < NT; it++) {
        const int s = it & 1;
        if (it + 1 < NT) { CP_WAIT1(); } else { CP_WAIT0(); }
        __syncthreads();

        const uint32_t cKhiA = sKa  + (s * 2 + 0) * A_STG * 2;
        const uint32_t cKloA = sKa  + (s * 2 + 1) * A_STG * 2;
        const uint32_t cVhiA = sVTa + (s * 2 + 0) * A_STG * 2;
        const uint32_t cVloA = sVTa + (s * 2 + 1) * A_STG * 2;
        const uint32_t bOff  = ((uint32_t)brow * ASTR + bcol) * 2;

        // --- S = Q K^T (3 split terms) ---
        float sc[8][4];
#pragma unroll
        for (int ni = 0; ni < 8; ni++)
#pragma unroll
            for (int j = 0; j < 4; j++) sc[ni][j] = 0.f;

#pragma unroll
        for (int kj = 0; kj < 4; kj++) {
#pragma unroll
            for (int np = 0; np < 4; np++) {
                uint32_t off = bOff + ((uint32_t)np * 16 * ASTR + 16 * kj) * 2;
                uint32_t h0[2], h1[2], l0_[2], l1_[2];
                ldsm_x4(h0[0], h0[1], h1[0], h1[1], cKhiA + off);
                ldsm_x4(l0_[0], l0_[1], l1_[0], l1_[1], cKloA + off);
                mma16816(sc[2 * np],     qh[kj], h0);
                mma16816(sc[2 * np],     qh[kj], l0_);
                mma16816(sc[2 * np],     ql[kj], h0);
                mma16816(sc[2 * np + 1], qh[kj], h1);
                mma16816(sc[2 * np + 1], qh[kj], l1_);
                mma16816(sc[2 * np + 1], ql[kj], h1);
            }
        }

        // --- online softmax ---
        float mx0 = -1e30f, mx1 = -1e30f;
#pragma unroll
        for (int ni = 0; ni < 8; ni++) {
            sc[ni][0] *= 0.125f; sc[ni][1] *= 0.125f;
            sc[ni][2] *= 0.125f; sc[ni][3] *= 0.125f;
            mx0 = fmaxf(mx0, fmaxf(sc[ni][0], sc[ni][1]));
            mx1 = fmaxf(mx1, fmaxf(sc[ni][2], sc[ni][3]));
        }
        mx0 = fmaxf(mx0, __shfl_xor_sync(0xffffffff, mx0, 1));
        mx0 = fmaxf(mx0, __shfl_xor_sync(0xffffffff, mx0, 2));
        mx1 = fmaxf(mx1, __shfl_xor_sync(0xffffffff, mx1, 1));
        mx1 = fmaxf(mx1, __shfl_xor_sync(0xffffffff, mx1, 2));

        const float nm0 = fmaxf(m0, mx0);
        const float nm1 = fmaxf(m1, mx1);
        const float rs0 = __expf(m0 - nm0);
        const float rs1 = __expf(m1 - nm1);
        m0 = nm0; m1 = nm1;
        l0 *= rs0; l1 *= rs1;
#pragma unroll
        for (int ni = 0; ni < 8; ni++) {
            o[ni][0] *= rs0; o[ni][1] *= rs0;
            o[ni][2] *= rs1; o[ni][3] *= rs1;
            sc[ni][0] = __expf(sc[ni][0] - m0);
            sc[ni][1] = __expf(sc[ni][1] - m0);
            sc[ni][2] = __expf(sc[ni][2] - m1);
            sc[ni][3] = __expf(sc[ni][3] - m1);
            l0 += sc[ni][0] + sc[ni][1];
            l1 += sc[ni][2] + sc[ni][3];
        }

        // --- O += P V (3 split terms) ---
#pragma unroll
        for (int kj = 0; kj < 4; kj++) {
            uint32_t ah[4], al[4];
            hilo2(sc[2 * kj][0],     sc[2 * kj][1],     ah[0], al[0]);
            hilo2(sc[2 * kj][2],     sc[2 * kj][3],     ah[1], al[1]);
            hilo2(sc[2 * kj + 1][0], sc[2 * kj + 1][1], ah[2], al[2]);
            hilo2(sc[2 * kj + 1][2], sc[2 * kj + 1][3], ah[3], al[3]);
#pragma unroll
            for (int np = 0; np < 4; np++) {
                uint32_t off = bOff + ((uint32_t)np * 16 * ASTR + 16 * kj) * 2;
                uint32_t h0[2], h1[2], l0_[2], l1_[2];
                ldsm_x4(h0[0], h0[1], h1[0], h1[1], cVhiA + off);
                ldsm_x4(l0_[0], l0_[1], l1_[0], l1_[1], cVloA + off);
                mma16816(o[2 * np],     ah, h0);
                mma16816(o[2 * np],     ah, l0_);
                mma16816(o[2 * np],     al, h0);
                mma16816(o[2 * np + 1], ah, h1);
                mma16816(o[2 * np + 1], ah, l1_);
                mma16816(o[2 * np + 1], al, h1);
            }
        }

        __syncthreads();
        if (it + 2 < NT) stage(s, (it + 2) * 64);
    }

    // --- finalize ---
    l0 += __shfl_xor_sync(0xffffffff, l0, 1);
    l0 += __shfl_xor_sync(0xffffffff, l0, 2);
    l1 += __shfl_xor_sync(0xffffffff, l1, 1);
    l1 += __shfl_xor_sync(0xffffffff, l1, 2);
    const float inv0 = 1.f / l0;
    const float inv1 = 1.f / l1;

    const int s0 = qt * 64 + wid * 16 + g;
    const int b  = bh >> 4;
    const int h  = bh & 15;
    const size_t row0 = (size_t)(b * SEQ + s0) * K3;
    const size_t row1 = row0 + (size_t)8 * K3;

#pragma unroll
    for (int ni = 0; ni < 8; ni++) {
        const int col = h * 64 + 8 * ni + 2 * t;
        uint32_t hi0, lo0, hi1, lo1;
        hilo2(o[ni][0] * inv0, o[ni][1] * inv0, hi0, lo0);
        hilo2(o[ni][2] * inv1, o[ni][3] * inv1, hi1, lo1);
        *(uint32_t*)&Out[row0 + col]        = hi0;
        *(uint32_t*)&Out[row0 + col + 1024] = hi0;
        *(uint32_t*)&Out[row0 + col + 2048] = lo0;
        *(uint32_t*)&Out[row1 + col]        = hi1;
        *(uint32_t*)&Out[row1 + col + 1024] = hi1;
        *(uint32_t*)&Out[row1 + col + 2048] = lo1;
    }
}

// ---------------------------------------------------------------------------
extern "C" void kernel_launch(void* const* d_in, const int* in_sizes, int n_in,
                              void* d_out, int out_size)
{
    const float* X   = (const float*)d_in[0];
    const float* W_q = (const float*)d_in[1];
    const float* b_q = (const float*)d_in[2];
    const float* W_k = (const float*)d_in[3];
    const float* b_k = (const float*)d_in[4];
    const float* W_v = (const float*)d_in[5];
    const float* b_v = (const float*)d_in[6];
    const float* W_o = (const float*)d_in[7];
    const float* b_o = (const float*)d_in[8];
    float* out = (float*)d_out;

    __nv_bfloat16 *Qhi, *Qlo, *Khi, *Klo, *VThi, *VTlo, *Xs, *Ws, *As;
    cudaGetSymbolAddress((void**)&Qhi, g_Qhi);
    cudaGetSymbolAddress((void**)&Qlo, g_Qlo);
    cudaGetSymbolAddress((void**)&Khi, g_Khi);
    cudaGetSymbolAddress((void**)&Klo, g_Klo);
    cudaGetSymbolAddress((void**)&VThi, g_VThi);
    cudaGetSymbolAddress((void**)&VTlo, g_VTlo);
    cudaGetSymbolAddress((void**)&Xs, g_Xs);
    cudaGetSymbolAddress((void**)&Ws, g_Ws);
    cudaGetSymbolAddress((void**)&As, g_As);

    cudaFuncSetAttribute(gemm_mma_kernel, cudaFuncAttributeMaxDynamicSharedMemorySize, G_SMEM);
    cudaFuncSetAttribute(attn_mma_kernel, cudaFuncAttributeMaxDynamicSharedMemorySize, ATT_SMEM);

    const int cthr = 256;
    split_x_kernel<<<MROWS * EMB / cthr, cthr>>>(X, Xs);
    dim3 wgrid(EMB * EMB / cthr, 4);
    split_w_kernel<<<wgrid, cthr>>>(W_q, W_k, W_v, W_o, Ws);

    // fused QKV (V written pre-transposed)
    dim3 qkvgrid(K3 / 128, MROWS / 128);
    gemm_mma_kernel<<<qkvgrid, 256, G_SMEM>>>(Xs, Ws, b_q, b_k, b_v,
                                              Qhi, Qlo, Khi, Klo, VThi, VTlo, nullptr, 0);

    dim3 agrid(SEQ / 64, BATCH * NHEAD);
    attn_mma_kernel<<<agrid, 128, ATT_SMEM>>>(Qhi, Qlo, Khi, Klo, VThi, VTlo, As);

    dim3 ogrid(EMB / 128, MROWS / 128);
    gemm_mma_kernel<<<ogrid, 256, G_SMEM>>>(As, Ws + 3 * (size_t)EMB * K3, b_o, nullptr, nullptr,
                                            nullptr, nullptr, nullptr, nullptr, nullptr, nullptr,
                                            out, 1);
}